// round 14
// baseline (speedup 1.0000x reference)
#include <cuda_runtime.h>
#include <cuda_bf16.h>
#include <cstdint>

// AllZeroDigitalFilter: time-varying FIR, y = A0 + w*(A1-A0).
// R13 "dual packing": accumulators are sample-pairs (A0[s],A0[s+1]) packed in
// f32x2; x operands are adjacent-sample pairs (mostly free register pairs from
// float4 window chunks); coefficients stored PRE-SPLATTED in smem as
// (b0,b0,b1,b1) per tap -> one LDS.128 broadcast = both splat operands, 0 MOVs.

#define TAPS         50
#define TAPS_PAD     52
#define NGROUPS      (TAPS_PAD / 4)          // 13
#define FRAME_P      80
#define FRAMES_PER_BLOCK 8
#define SAMP_PER_BLOCK   (FRAMES_PER_BLOCK * FRAME_P)   // 640
#define SAMP_PER_THREAD  4
#define THREADS_PER_BLOCK (SAMP_PER_BLOCK / SAMP_PER_THREAD) // 160
#define XPAD         56                      // mult of 8, covers m >= -56
#define X_TILE       (SAMP_PER_BLOCK + XPAD + 8)        // 704

typedef unsigned long long u64;
typedef unsigned int u32;

__device__ __forceinline__ u64 pack2(float lo, float hi) {
    u64 r;
    asm("mov.b64 %0, {%1, %2};" : "=l"(r) : "f"(lo), "f"(hi));
    return r;
}
__device__ __forceinline__ void fma2(u64& acc, u64 a, u64 b) {
    asm("fma.rn.f32x2 %0, %1, %2, %0;" : "+l"(acc) : "l"(a), "l"(b));
}
__device__ __forceinline__ void unpack2(float& lo, float& hi, u64 v) {
    asm("mov.b64 {%0, %1}, %2;" : "=f"(lo), "=f"(hi) : "l"(v));
}
__device__ __forceinline__ u32 smem_addr32(const void* p) {
    return (u32)__cvta_generic_to_shared(p);
}
__device__ __forceinline__ void cp_async16(u32 saddr, const void* gaddr) {
    asm volatile("cp.async.cg.shared.global [%0], [%1], 16;"
                 :: "r"(saddr), "l"(gaddr) : "memory");
}

__global__ __launch_bounds__(THREADS_PER_BLOCK)
void azdf_kernel(const float* __restrict__ x,
                 const float* __restrict__ bcoef,
                 float* __restrict__ y,
                 int T, int N)
{
    __shared__ __align__(16) float xs[X_TILE];
    // cws[r][k] = (b[n0+r][k], b[n0+r][k], b[n0+r+1][k], b[n0+r+1][k])
    __shared__ __align__(16) float4 cws[FRAMES_PER_BLOCK][TAPS_PAD];

    const int bidx = blockIdx.y;
    const int t0   = blockIdx.x * SAMP_PER_BLOCK;
    const int n0   = blockIdx.x * FRAMES_PER_BLOCK;
    const int tid  = threadIdx.x;

    const float* xg = x + (size_t)bidx * T;
    const float* bg = bcoef + (size_t)bidx * N * TAPS;

    // ---- stage x tile: xs[i] = x[t0 - XPAD + i], zero-padded ----
    bool used_async = false;
    if (t0 >= XPAD && t0 + (X_TILE - XPAD) <= T) {
        const float* src = xg + t0 - XPAD;       // 16B aligned (t0-XPAD mult 8)
        #pragma unroll
        for (int i = tid; i < X_TILE / 4; i += THREADS_PER_BLOCK)
            cp_async16(smem_addr32(xs + 4 * i), src + 4 * i);
        asm volatile("cp.async.commit_group;" ::: "memory");
        used_async = true;
    } else {
        #pragma unroll
        for (int i = tid; i < X_TILE; i += THREADS_PER_BLOCK) {
            int g = t0 - XPAD + i;
            xs[i] = (g >= 0 && g < T) ? xg[g] : 0.0f;
        }
    }
    // ---- stage pre-splatted coeff quads (overlaps with async x loads) ----
    #pragma unroll
    for (int i = tid; i < FRAMES_PER_BLOCK * TAPS_PAD; i += THREADS_PER_BLOCK) {
        int r = i / TAPS_PAD;
        int k = i - r * TAPS_PAD;
        int n  = n0 + r;     if (n  > N - 1) n  = N - 1;
        int n1 = n0 + r + 1; if (n1 > N - 1) n1 = N - 1;
        float c0 = 0.0f, c1 = 0.0f;
        if (k < TAPS) {
            c0 = bg[(size_t)n  * TAPS + k];
            c1 = bg[(size_t)n1 * TAPS + k];
        }
        cws[r][k] = make_float4(c0, c0, c1, c1);
    }
    if (used_async)
        asm volatile("cp.async.wait_group 0;" ::: "memory");
    __syncthreads();

    const int ls = tid * SAMP_PER_THREAD;   // local sample base (mult of 4)
    const int fr = ls / FRAME_P;            // frame in block
    const int p  = ls - fr * FRAME_P;       // phase (mult of 4)

    const float4* xs4 = reinterpret_cast<const float4*>(xs);
    const float4* cf  = cws[fr];

    // Accumulator pairs: P00=(A0[0],A0[1]) P01=(A0[2],A0[3])
    //                    P10=(A1[0],A1[1]) P11=(A1[2],A1[3])
    u64 P00 = 0, P01 = 0, P10 = 0, P11 = 0;

    // Window: W[m] = xs[XPAD+ls+m]. Group g (taps k=4g+q) uses m in
    // [-4g-3, -4g+3]. Chunks: hi = W[-4g..-4g+3], lo = W[-4g-4..-4g-1].
    // Pair at offset off = (W[off], W[off+1]):
    //   E0=(lo.z,lo.w) E1=(hi.x,hi.y) E2=(hi.z,hi.w)   (even, reg-aligned)
    //   O0=(lo.y,lo.z) O1=(lo.w,hi.x) O2=(hi.y,hi.z)   (odd, packed)
    const int cbase = (XPAD + ls) / 4;
    float4 hi = xs4[cbase];
    float4 lo = xs4[cbase - 1];
    u64 O0 = pack2(lo.y, lo.z);
    u64 O1 = pack2(lo.w, hi.x);
    u64 O2 = pack2(hi.y, hi.z);

    #pragma unroll
    for (int g = 0; g < NGROUPS; ++g) {
        const u64 E0 = pack2(lo.z, lo.w);   // aligned: elided by ptxas
        const u64 E1 = pack2(hi.x, hi.y);
        const u64 E2 = pack2(hi.z, hi.w);

        // q = 0 (tap 4g):   pairs E1, E2
        {
            float4 c = cf[4 * g + 0];
            u64 c0s = pack2(c.x, c.y), c1s = pack2(c.z, c.w);
            fma2(P00, E1, c0s); fma2(P01, E2, c0s);
            fma2(P10, E1, c1s); fma2(P11, E2, c1s);
        }
        // q = 1 (tap 4g+1): pairs O1, O2
        {
            float4 c = cf[4 * g + 1];
            u64 c0s = pack2(c.x, c.y), c1s = pack2(c.z, c.w);
            fma2(P00, O1, c0s); fma2(P01, O2, c0s);
            fma2(P10, O1, c1s); fma2(P11, O2, c1s);
        }
        // q = 2 (tap 4g+2): pairs E0, E1
        {
            float4 c = cf[4 * g + 2];
            u64 c0s = pack2(c.x, c.y), c1s = pack2(c.z, c.w);
            fma2(P00, E0, c0s); fma2(P01, E1, c0s);
            fma2(P10, E0, c1s); fma2(P11, E1, c1s);
        }
        // q = 3 (tap 4g+3): pairs O0, O1
        {
            float4 c = cf[4 * g + 3];
            u64 c0s = pack2(c.x, c.y), c1s = pack2(c.z, c.w);
            fma2(P00, O0, c0s); fma2(P01, O1, c0s);
            fma2(P10, O0, c1s); fma2(P11, O1, c1s);
        }

        if (g < NGROUPS - 1) {
            // slide window down by one chunk
            hi = lo;
            O2 = O0;                          // (hi.y,hi.z) of next = (lo.y,lo.z)
            lo = xs4[cbase - g - 2];
            O0 = pack2(lo.y, lo.z);
            O1 = pack2(lo.w, hi.x);
        }
    }

    // ---- blend and store ----
    float a00, a01, a02, a03, a10, a11, a12, a13;
    unpack2(a00, a01, P00);
    unpack2(a02, a03, P01);
    unpack2(a10, a11, P10);
    unpack2(a12, a13, P11);

    const int tglob = t0 + ls;
    const float invP = 1.0f / (float)FRAME_P;
    if (tglob + SAMP_PER_THREAD <= T) {
        float4 r;
        r.x = fmaf((float)(p + 0) * invP, a10 - a00, a00);
        r.y = fmaf((float)(p + 1) * invP, a11 - a01, a01);
        r.z = fmaf((float)(p + 2) * invP, a12 - a02, a02);
        r.w = fmaf((float)(p + 3) * invP, a13 - a03, a03);
        *reinterpret_cast<float4*>(y + (size_t)bidx * T + tglob) = r;
    } else {
        float a0[4] = {a00, a01, a02, a03};
        float a1[4] = {a10, a11, a12, a13};
        #pragma unroll
        for (int s = 0; s < SAMP_PER_THREAD; ++s) {
            int t = tglob + s;
            if (t < T) {
                float ww = (float)(p + s) * invP;
                y[(size_t)bidx * T + t] = fmaf(ww, a1[s] - a0[s], a0[s]);
            }
        }
    }
}

extern "C" void kernel_launch(void* const* d_in, const int* in_sizes, int n_in,
                              void* d_out, int out_size)
{
    const float* x = (const float*)d_in[0];   // (B, T) float32
    const float* b = (const float*)d_in[1];   // (B, N, 50) float32
    float* y = (float*)d_out;                 // (B, T) float32

    const int B = 8;
    const int T = in_sizes[0] / B;
    const int N = in_sizes[1] / (B * TAPS);

    dim3 grid((T + SAMP_PER_BLOCK - 1) / SAMP_PER_BLOCK, B);
    azdf_kernel<<<grid, THREADS_PER_BLOCK>>>(x, b, y, T, N);
}